// round 10
// baseline (speedup 1.0000x reference)
#include <cuda_runtime.h>
#include <math_constants.h>

#define N_NODES 50000
#define N_EDGES 800000
#define D 64
#define DH 8
#define NSEG (N_NODES * DH)

typedef unsigned long long u64;

// Device scratch (no cudaMalloc allowed)
__device__ __align__(16) float g_q[N_NODES * D];
__device__ __align__(16) float g_k[N_NODES * D];
__device__ __align__(16) float g_s[NSEG];

// ---- Blackwell packed f32x2 helpers (FFMA2: only reachable via PTX) ----
__device__ __forceinline__ u64 pack2(float lo, float hi) {
    u64 r; asm("mov.b64 %0, {%1, %2};" : "=l"(r) : "f"(lo), "f"(hi)); return r;
}
__device__ __forceinline__ u64 fma2(u64 a, u64 b, u64 c) {
    u64 r; asm("fma.rn.f32x2 %0, %1, %2, %3;" : "=l"(r) : "l"(a), "l"(b), "l"(c)); return r;
}
__device__ __forceinline__ u64 add2(u64 a, u64 b) {
    u64 r; asm("add.rn.f32x2 %0, %1, %2;" : "=l"(r) : "l"(a), "l"(b)); return r;
}

// ---------------------------------------------------------------------------
// QK GEMM: x[N,64] @ {Wq,Wk}[64,64] + bias. 128 thr, 64 nodes/block,
// thread tile 4 cols x 8 nodes x 2 mats (acc 64 regs). 48KB smem ->
// 4 blocks/SM = 16 warps. Also zero-inits g_s.
// ---------------------------------------------------------------------------
__global__ __launch_bounds__(128, 4) void qk_gemm_kernel(
    const float* __restrict__ x,
    const float* __restrict__ Wq, const float* __restrict__ bq,
    const float* __restrict__ Wk, const float* __restrict__ bk)
{
    __shared__ __align__(16) float sW[2 * D * D];   // Wq | Wk
    __shared__ __align__(16) float sx[64 * D];

    const int tid = threadIdx.x;
    const int n0 = blockIdx.x * 64;

    // Fused init: zero g_s (100000 float4; 782*128 = 100096 thr)
    {
        int gtid = blockIdx.x * 128 + tid;
        if (gtid < NSEG / 4) {
            ((float4*)g_s)[gtid] = make_float4(0.f, 0.f, 0.f, 0.f);
        }
    }

    {
        const float4* wq4 = (const float4*)Wq;
        const float4* wk4 = (const float4*)Wk;
        float4* s4 = (float4*)sW;
#pragma unroll
        for (int i = tid; i < 1024; i += 128) {
            s4[i]        = wq4[i];
            s4[1024 + i] = wk4[i];
        }
    }
    {
        float4* sx4 = (float4*)sx;
        const float4* x4 = (const float4*)x;
#pragma unroll
        for (int i = tid; i < 1024; i += 128) {
            int node = i >> 4;
            int gn = n0 + node;
            sx4[i] = (gn < N_NODES) ? x4[(size_t)gn * 16 + (i & 15)]
                                    : make_float4(0.f, 0.f, 0.f, 0.f);
        }
    }
    __syncthreads();

    const int cx = (tid & 15) * 4;
    const int ny = tid >> 4;

    u64 acc[2][8][2];
#pragma unroll
    for (int m = 0; m < 2; m++)
#pragma unroll
        for (int j = 0; j < 8; j++) { acc[m][j][0] = 0ull; acc[m][j][1] = 0ull; }

#pragma unroll 4
    for (int i4 = 0; i4 < 16; i4++) {
        float xa[8][4];
#pragma unroll
        for (int j = 0; j < 8; j++) {
            *(float4*)xa[j] = *(const float4*)&sx[(ny + 8 * j) * D + i4 * 4];
        }
#pragma unroll
        for (int ii = 0; ii < 4; ii++) {
            const int i = i4 * 4 + ii;
            ulonglong2 wq = *(const ulonglong2*)&sW[i * D + cx];
            ulonglong2 wk = *(const ulonglong2*)&sW[D * D + i * D + cx];
#pragma unroll
            for (int j = 0; j < 8; j++) {
                float xs = xa[j][ii];
                u64 x2 = pack2(xs, xs);
                acc[0][j][0] = fma2(x2, wq.x, acc[0][j][0]);
                acc[0][j][1] = fma2(x2, wq.y, acc[0][j][1]);
                acc[1][j][0] = fma2(x2, wk.x, acc[1][j][0]);
                acc[1][j][1] = fma2(x2, wk.y, acc[1][j][1]);
            }
        }
    }

    ulonglong2 bq2 = *(const ulonglong2*)&bq[cx];
    ulonglong2 bk2 = *(const ulonglong2*)&bk[cx];

#pragma unroll
    for (int j = 0; j < 8; j++) {
        int node = n0 + ny + 8 * j;
        if (node < N_NODES) {
            *(u64*)&g_q[node * D + cx]     = add2(acc[0][j][0], bq2.x);
            *(u64*)&g_q[node * D + cx + 2] = add2(acc[0][j][1], bq2.y);
            *(u64*)&g_k[node * D + cx]     = add2(acc[1][j][0], bk2.x);
            *(u64*)&g_k[node * D + cx + 2] = add2(acc[1][j][1], bk2.y);
        }
    }
}

// ---------------------------------------------------------------------------
// V GEMM: x[N,64] @ Wv[64,64] + bias -> vout (d_out region).
// Runs on a side stream, overlapped with edge_fused (complementary pipes).
// ---------------------------------------------------------------------------
__global__ __launch_bounds__(128, 6) void v_gemm_kernel(
    const float* __restrict__ x,
    const float* __restrict__ Wv, const float* __restrict__ bv,
    float* __restrict__ vout)
{
    __shared__ __align__(16) float sW[D * D];
    __shared__ __align__(16) float sx[64 * D];

    const int tid = threadIdx.x;
    const int n0 = blockIdx.x * 64;

    {
        const float4* wv4 = (const float4*)Wv;
        float4* s4 = (float4*)sW;
#pragma unroll
        for (int i = tid; i < 1024; i += 128) s4[i] = wv4[i];
    }
    {
        float4* sx4 = (float4*)sx;
        const float4* x4 = (const float4*)x;
#pragma unroll
        for (int i = tid; i < 1024; i += 128) {
            int node = i >> 4;
            int gn = n0 + node;
            sx4[i] = (gn < N_NODES) ? x4[(size_t)gn * 16 + (i & 15)]
                                    : make_float4(0.f, 0.f, 0.f, 0.f);
        }
    }
    __syncthreads();

    const int cx = (tid & 15) * 4;
    const int ny = tid >> 4;

    u64 acc[8][2];
#pragma unroll
    for (int j = 0; j < 8; j++) { acc[j][0] = 0ull; acc[j][1] = 0ull; }

#pragma unroll 4
    for (int i4 = 0; i4 < 16; i4++) {
        float xa[8][4];
#pragma unroll
        for (int j = 0; j < 8; j++) {
            *(float4*)xa[j] = *(const float4*)&sx[(ny + 8 * j) * D + i4 * 4];
        }
#pragma unroll
        for (int ii = 0; ii < 4; ii++) {
            const int i = i4 * 4 + ii;
            ulonglong2 wv = *(const ulonglong2*)&sW[i * D + cx];
#pragma unroll
            for (int j = 0; j < 8; j++) {
                float xs = xa[j][ii];
                u64 x2 = pack2(xs, xs);
                acc[j][0] = fma2(x2, wv.x, acc[j][0]);
                acc[j][1] = fma2(x2, wv.y, acc[j][1]);
            }
        }
    }

    ulonglong2 bv2 = *(const ulonglong2*)&bv[cx];

#pragma unroll
    for (int j = 0; j < 8; j++) {
        int node = n0 + ny + 8 * j;
        if (node < N_NODES) {
            *(u64*)&vout[node * D + cx]     = add2(acc[j][0], bv2.x);
            *(u64*)&vout[node * D + cx + 2] = add2(acc[j][1], bv2.y);
        }
    }
}

// ---------------------------------------------------------------------------
// Warp-cooperative fused edge pass: logits + exp + vec4-atomic segment sum.
// 8 lanes per edge, 4 edges per warp; all gathers coalesced.
// ---------------------------------------------------------------------------
__global__ __launch_bounds__(256) void edge_fused_kernel(
    const int* __restrict__ edge, float* __restrict__ prods)
{
    const int lane = threadIdx.x & 31;
    const int warp = (blockIdx.x * 256 + threadIdx.x) >> 5;
    const int e0   = warp * 4;
    const int sub  = lane >> 3;
    const int d    = lane & 7;
    const int e    = e0 + sub;

    const int src = edge[e];
    const int dst = edge[N_EDGES + e];

    const float4* q4 = (const float4*)(g_q + src * D);
    const float4* k4 = (const float4*)(g_k + dst * D);

    float4 qa = q4[d];
    float4 qb = q4[d + 8];
    float4 ka = k4[d];
    float4 kb = k4[d + 8];

    float w0 = qa.x * ka.x + qb.x * kb.x;
    float w1 = qa.y * ka.y + qb.y * kb.y;
    float w2 = qa.z * ka.z + qb.z * kb.z;
    float w3 = qa.w * ka.w + qb.w * kb.w;

    const unsigned FULL = 0xffffffffu;

    {
        float t0 = (lane & 4) ? w0 : w2;
        float t1 = (lane & 4) ? w1 : w3;
        float u0 = __shfl_xor_sync(FULL, t0, 4);
        float u1 = __shfl_xor_sync(FULL, t1, 4);
        w0 = ((lane & 4) ? w2 : w0) + u0;
        w1 = ((lane & 4) ? w3 : w1) + u1;
    }
    float p;
    {
        float t2 = (lane & 2) ? w0 : w1;
        float u2 = __shfl_xor_sync(FULL, t2, 2);
        p = ((lane & 2) ? w1 : w0) + u2;
    }
    {
        int srcl = (sub << 3) | ((d >> 2) & 1) | ((d & 1) << 1) | ((d & 2) << 1);
        p = __shfl_sync(FULL, p, srcl);
    }

    p *= 0.35355339059327373f;  // 1/sqrt(8)

    size_t off = (size_t)e0 * 8 + lane;
    prods[off] = p;
    float ev = __expf(p);

    float p1 = __shfl_down_sync(FULL, ev, 1);
    float p2 = __shfl_down_sync(FULL, ev, 2);
    float p3 = __shfl_down_sync(FULL, ev, 3);
    if ((lane & 3) == 0) {
        float* srow = g_s + dst * 8 + (lane & 4);
        asm volatile("red.global.add.v4.f32 [%0], {%1, %2, %3, %4};"
                     :: "l"(srow), "f"(ev), "f"(p1), "f"(p2), "f"(p3) : "memory");
    }
}

// ---------------------------------------------------------------------------
// Pass C: att[e][d] = exp(prods[e][d]) / (s[dst][d] + 1e-16).
// ---------------------------------------------------------------------------
__global__ __launch_bounds__(256) void edge_scale_kernel(
    const int* __restrict__ edge, const float* __restrict__ prods,
    float* __restrict__ att)
{
    int e = blockIdx.x * blockDim.x + threadIdx.x;
    if (e >= N_EDGES) return;
    int dst = edge[N_EDGES + e];

    const float4* sr = (const float4*)(g_s + dst * 8);
    float4 s0 = sr[0];
    float4 s1 = sr[1];

    const float4* pr = (const float4*)(prods + (size_t)e * 8);
    float4 p0 = pr[0];
    float4 p1 = pr[1];

    float4 v0, v1;
    v0.x = __fdividef(__expf(p0.x), s0.x + 1e-16f);
    v0.y = __fdividef(__expf(p0.y), s0.y + 1e-16f);
    v0.z = __fdividef(__expf(p0.z), s0.z + 1e-16f);
    v0.w = __fdividef(__expf(p0.w), s0.w + 1e-16f);
    v1.x = __fdividef(__expf(p1.x), s1.x + 1e-16f);
    v1.y = __fdividef(__expf(p1.y), s1.y + 1e-16f);
    v1.z = __fdividef(__expf(p1.z), s1.z + 1e-16f);
    v1.w = __fdividef(__expf(p1.w), s1.w + 1e-16f);

    float4* ar = (float4*)(att + (size_t)e * 8);
    ar[0] = v0;
    ar[1] = v1;
}

// ---------------------------------------------------------------------------
// kernel_launch
// Inputs (metadata order): x, Wq, bq, Wk, bk, Wv, bv, edge
// Output: attention [E,8] | v [N,8,8] | prods [E,8]  (float32)
//
// Stream plan (all graph-capturable):
//   main: qk_gemm -> edge_fused -> edge_scale
//   s2:   (fork after qk_gemm) v_gemm  (overlaps edge_fused; joined at end)
// ---------------------------------------------------------------------------
extern "C" void kernel_launch(void* const* d_in, const int* in_sizes, int n_in,
                              void* d_out, int out_size) {
    const float* x  = (const float*)d_in[0];
    const float* Wq = (const float*)d_in[1];
    const float* bq = (const float*)d_in[2];
    const float* Wk = (const float*)d_in[3];
    const float* bk = (const float*)d_in[4];
    const float* Wv = (const float*)d_in[5];
    const float* bv = (const float*)d_in[6];
    const int*   edge = (const int*)d_in[7];

    float* out   = (float*)d_out;
    float* att   = out;                          // E*8
    float* vout  = out + (size_t)N_EDGES * 8;    // N*64
    float* prods = vout + (size_t)N_NODES * 64;  // E*8

    // Lazy one-time creation of side stream + events (host objects, not
    // device memory; created on the uncaptured correctness call, reused
    // identically every call thereafter).
    static cudaStream_t s2 = nullptr;
    static cudaEvent_t evFork = nullptr, evJoin = nullptr;
    if (s2 == nullptr) {
        cudaStreamCreateWithFlags(&s2, cudaStreamNonBlocking);
        cudaEventCreateWithFlags(&evFork, cudaEventDisableTiming);
        cudaEventCreateWithFlags(&evJoin, cudaEventDisableTiming);
    }

    qk_gemm_kernel<<<(N_NODES + 63) / 64, 128>>>(x, Wq, bq, Wk, bk);

    // Fork: v_gemm on s2, overlapping edge_fused on the main stream.
    cudaEventRecord(evFork, 0);
    cudaStreamWaitEvent(s2, evFork, 0);
    v_gemm_kernel<<<(N_NODES + 63) / 64, 128, 0, s2>>>(x, Wv, bv, vout);
    cudaEventRecord(evJoin, s2);

    edge_fused_kernel<<<N_EDGES / 32, 256>>>(edge, prods);
    edge_scale_kernel<<<(N_EDGES + 255) / 256, 256>>>(edge, prods, att);

    // Join: main stream waits for v_gemm before the graph's end.
    cudaStreamWaitEvent(0, evJoin, 0);
}